// round 17
// baseline (speedup 1.0000x reference)
#include <cuda_runtime.h>
#include <cstdint>

// SplitMLP R15: R14 pipeline + day-operand-in-registers + 3 CTAs/SM + GPC=8.
//   1250 CTAs x 8 groups (g = i*1250 + bx). fc1 = mma.sync tf32 m16n8k8, fc2 in regs.
//   day A-fragments: 16 regs/thread, loaded once per CTA (L2-resident), no smem tile.
//   itS[2][b][v] pitch 36 (frag banks 4r+q conflict-free), cp.async double-buffered.
//   WsS[2][j][k] pitch 52 (frag banks 20r+q conflict-free), cp.async double-buffered.
//   smem 64.6KB -> 3 CTAs/SM; __launch_bounds__(128,3) caps regs at 170.

#define NG   10000
#define NCTA 1250
#define GPC  8
#define PIT  36
#define PW   52

// float offsets in dynamic smem
#define F_IT  0            // 2 * (128*36 = 4608)
#define F_WS  9216         // 2 * (64*52 = 3328)
#define F_W2  15872        // 2 * 256
#define F_B1  16384        // 2 * 64
#define F_B2  16512        // 2 * 8
#define SMEM_FLOATS 16528
#define SMEM_BYTES (SMEM_FLOATS * 4)   // 66112 B

typedef unsigned long long ull;
typedef unsigned int uint;

#define FMA2(d, a, b, c) \
    asm("fma.rn.f32x2 %0, %1, %2, %3;" : "=l"(d) : "l"(a), "l"(b), "l"(c))
#define ADD2(d, a, b) \
    asm("add.rn.f32x2 %0, %1, %2;" : "=l"(d) : "l"(a), "l"(b))
#define PACK2(d, x) \
    asm("mov.b64 %0, {%1, %1};" : "=l"(d) : "f"(x))
#define UNPACK2(lo, hi, v) \
    asm("mov.b64 {%0, %1}, %2;" : "=f"(lo), "=f"(hi) : "l"(v))
#define CPASYNC16(dst_u32, src_gptr) \
    asm volatile("cp.async.cg.shared.global [%0], [%1], 16;" \
                 :: "r"(dst_u32), "l"(src_gptr) : "memory")

__device__ __forceinline__ uint smem_u32(const void* p) {
    uint a;
    asm("{ .reg .u64 t; cvta.to.shared.u64 t, %1; cvt.u32.u64 %0, t; }" : "=r"(a) : "l"(p));
    return a;
}

__device__ __forceinline__ void mma_tf32(float& d0, float& d1, float& d2, float& d3,
                                         uint a0, uint a1, uint a2, uint a3,
                                         uint b0, uint b1) {
    asm volatile(
        "mma.sync.aligned.m16n8k8.row.col.f32.tf32.tf32.f32 "
        "{%0,%1,%2,%3}, {%4,%5,%6,%7}, {%8,%9}, {%0,%1,%2,%3};"
        : "+f"(d0), "+f"(d1), "+f"(d2), "+f"(d3)
        : "r"(a0), "r"(a1), "r"(a2), "r"(a3), "r"(b0), "r"(b1));
}

__device__ __forceinline__ ull bfly_add2(ull v, int m) {
    float lo, hi;
    UNPACK2(lo, hi, v);
    uint lo2 = __shfl_xor_sync(0xffffffffu, __float_as_uint(lo), m);
    uint hi2 = __shfl_xor_sync(0xffffffffu, __float_as_uint(hi), m);
    ull o;
    asm("mov.b64 %0, {%1, %2};" : "=l"(o) : "r"(lo2), "r"(hi2));
    ull r;
    ADD2(r, v, o);
    return r;
}

__global__ __launch_bounds__(128, 3)
void splitmlp_kernel(const float* __restrict__ day,
                     const float* __restrict__ items,
                     const float* __restrict__ W1d,
                     const float* __restrict__ W1v,
                     const float* __restrict__ b1,
                     const float* __restrict__ W2,
                     const float* __restrict__ b2,
                     float* __restrict__ out)
{
    extern __shared__ __align__(16) float smem[];
    const int bx = blockIdx.x;
    const int t  = threadIdx.x;
    const int lane = t & 31, w = t >> 5;
    const int r = lane >> 2, q = lane & 3;
    const int m0 = w * 32;

    const uint sb = smem_u32(smem);

    // per-thread staging index constants (strength-reduced)
    const int sb0 = t >> 3, sq = t & 7;    // items / W1v
    const int wj0 = t >> 2, wcq = t & 3;   // W1d

    // ---- day A-fragments in registers (once per CTA; day is L2-resident) ----
    uint df[2][2][4];   // [ks][mt][frag]
    {
        const uint* dayu = (const uint*)day;
        #pragma unroll
        for (int ks = 0; ks < 2; ks++)
            #pragma unroll
            for (int mt = 0; mt < 2; mt++) {
                const int row = m0 + mt * 16 + r;
                df[ks][mt][0] = dayu[row * 16 + 8 * ks + q];
                df[ks][mt][1] = dayu[(row + 8) * 16 + 8 * ks + q];
                df[ks][mt][2] = dayu[row * 16 + 8 * ks + 4 + q];
                df[ks][mt][3] = dayu[(row + 8) * 16 + 8 * ks + 4 + q];
            }
    }

    // ---- helper: cp.async prefetch of group g into buffer buf ----
    auto issue_group = [&](int buf, int g) {
        const uint itb = sb + (uint)(F_IT + buf * 4608) * 4u;
        const uint wsb = sb + (uint)(F_WS + buf * 3328) * 4u;
        {   // items: 8 x 16B per thread
            const float4* src = (const float4*)items
                              + (size_t)sb0 * (NG * 8) + (size_t)g * 8 + sq;
            #pragma unroll
            for (int i = 0; i < 8; i++)
                CPASYNC16(itb + (uint)((sb0 + 16 * i) * PIT + 4 * sq) * 4u,
                          src + (size_t)(16 * i) * (NG * 8));
        }
        {   // W1v: 4 x 16B -> Ws[j][16+4vq]
            const float4* src = (const float4*)W1v + (size_t)g * 512 + sb0 * 8 + sq;
            #pragma unroll
            for (int i = 0; i < 4; i++)
                CPASYNC16(wsb + (uint)((sb0 + 16 * i) * PW + 16 + 4 * sq) * 4u,
                          src + 16 * i * 8);
        }
        {   // W1d: 2 x 16B -> Ws[j][4cq]
            const float4* src = (const float4*)W1d + (size_t)g * 256 + wj0 * 4 + wcq;
            #pragma unroll
            for (int i = 0; i < 2; i++)
                CPASYNC16(wsb + (uint)((wj0 + 32 * i) * PW + 4 * wcq) * 4u,
                          src + 32 * i * 4);
        }
    };

    // ---- prologue: group 0 ----
    issue_group(0, bx);
    asm volatile("cp.async.commit_group;" ::: "memory");

    float4 w2reg;
    float b1reg = 0.0f, b2reg = 0.0f;
    {
        const int g0 = bx;
        if (t < 64) {
            int o = t >> 4, jq = t & 15;
            w2reg = ((const float4*)W2)[(size_t)g0 * 64 + o * 16 + jq];
        } else {
            b1reg = b1[(size_t)g0 * 64 + (t - 64)];
        }
        if (t < 4) b2reg = b2[(size_t)g0 * 4 + t];
        float* W2sT = smem + F_W2;
        float* b1s  = smem + F_B1;
        float* b2s  = smem + F_B2;
        if (t < 64) {
            int o = t >> 4, jq = t & 15;
            W2sT[(4 * jq + 0) * 4 + o] = w2reg.x;
            W2sT[(4 * jq + 1) * 4 + o] = w2reg.y;
            W2sT[(4 * jq + 2) * 4 + o] = w2reg.z;
            W2sT[(4 * jq + 3) * 4 + o] = w2reg.w;
        } else {
            b1s[t - 64] = b1reg;
        }
        if (t < 4) b2s[t] = b2reg;
    }

    // ---- main pipeline ----
    for (int i = 0; i < GPC; i++) {
        const int buf = i & 1;
        const int g = i * NCTA + bx;
        const bool has_next = (i + 1 < GPC);

        asm volatile("cp.async.wait_group 0;" ::: "memory");
        __syncthreads();

        if (has_next) {
            issue_group(buf ^ 1, g + NCTA);
            asm volatile("cp.async.commit_group;" ::: "memory");
            const int gn = g + NCTA;
            if (t < 64) {
                int o = t >> 4, jq = t & 15;
                w2reg = ((const float4*)W2)[(size_t)gn * 64 + o * 16 + jq];
            } else {
                b1reg = b1[(size_t)gn * 64 + (t - 64)];
            }
            if (t < 4) b2reg = b2[(size_t)gn * 4 + t];
        }

        // ================= fc1: mma.sync tf32 =================
        const uint* itU = (const uint*)(smem + F_IT + buf * 4608);
        const uint* Wu  = (const uint*)(smem + F_WS + buf * 3328);

        float d[2][8][4];
        #pragma unroll
        for (int mt = 0; mt < 2; mt++)
            #pragma unroll
            for (int nt = 0; nt < 8; nt++)
                #pragma unroll
                for (int c = 0; c < 4; c++) d[mt][nt][c] = 0.0f;

        // ks 0..1: day operand from registers
        #pragma unroll
        for (int ks = 0; ks < 2; ks++) {
            const int k0 = ks * 8;
            uint bf[8][2];
            #pragma unroll
            for (int nt = 0; nt < 8; nt++) {
                bf[nt][0] = Wu[(nt * 8 + r) * PW + k0 + q];
                bf[nt][1] = Wu[(nt * 8 + r) * PW + k0 + 4 + q];
            }
            #pragma unroll
            for (int mt = 0; mt < 2; mt++)
                #pragma unroll
                for (int nt = 0; nt < 8; nt++)
                    mma_tf32(d[mt][nt][0], d[mt][nt][1], d[mt][nt][2], d[mt][nt][3],
                             df[ks][mt][0], df[ks][mt][1], df[ks][mt][2], df[ks][mt][3],
                             bf[nt][0], bf[nt][1]);
        }
        // ks 2..5: items operand from smem
        #pragma unroll
        for (int ks = 2; ks < 6; ks++) {
            const int k0 = ks * 8;
            const int ak = k0 - 16;
            uint bf[8][2];
            #pragma unroll
            for (int nt = 0; nt < 8; nt++) {
                bf[nt][0] = Wu[(nt * 8 + r) * PW + k0 + q];
                bf[nt][1] = Wu[(nt * 8 + r) * PW + k0 + 4 + q];
            }
            #pragma unroll
            for (int mt = 0; mt < 2; mt++) {
                const int row = m0 + mt * 16 + r;
                uint a0 = itU[row * PIT + ak + q];
                uint a1 = itU[(row + 8) * PIT + ak + q];
                uint a2 = itU[row * PIT + ak + 4 + q];
                uint a3 = itU[(row + 8) * PIT + ak + 4 + q];
                #pragma unroll
                for (int nt = 0; nt < 8; nt++)
                    mma_tf32(d[mt][nt][0], d[mt][nt][1], d[mt][nt][2], d[mt][nt][3],
                             a0, a1, a2, a3, bf[nt][0], bf[nt][1]);
            }
        }

        // ================= bias + relu + fc2 (registers) =================
        const float* W2sT = smem + F_W2 + buf * 256;
        const float* b1s  = smem + F_B1 + buf * 64;
        const float* b2s  = smem + F_B2 + buf * 8;

        ull y01[4], y23[4];
        #pragma unroll
        for (int ii = 0; ii < 4; ii++) { y01[ii] = 0ULL; y23[ii] = 0ULL; }

        #pragma unroll
        for (int nt = 0; nt < 8; nt++) {
            const int j0 = nt * 8 + 2 * q;
            float2 bb = *(const float2*)&b1s[j0];
            ulonglong2 wj0v = *(const ulonglong2*)&W2sT[j0 * 4];
            ulonglong2 wj1v = *(const ulonglong2*)&W2sT[(j0 + 1) * 4];
            #pragma unroll
            for (int mt = 0; mt < 2; mt++) {
                {
                    float h0 = fmaxf(d[mt][nt][0] + bb.x, 0.0f);
                    float h1 = fmaxf(d[mt][nt][1] + bb.y, 0.0f);
                    ull h;
                    PACK2(h, h0);
                    FMA2(y01[mt * 2], h, wj0v.x, y01[mt * 2]);
                    FMA2(y23[mt * 2], h, wj0v.y, y23[mt * 2]);
                    PACK2(h, h1);
                    FMA2(y01[mt * 2], h, wj1v.x, y01[mt * 2]);
                    FMA2(y23[mt * 2], h, wj1v.y, y23[mt * 2]);
                }
                {
                    float h0 = fmaxf(d[mt][nt][2] + bb.x, 0.0f);
                    float h1 = fmaxf(d[mt][nt][3] + bb.y, 0.0f);
                    ull h;
                    PACK2(h, h0);
                    FMA2(y01[mt * 2 + 1], h, wj0v.x, y01[mt * 2 + 1]);
                    FMA2(y23[mt * 2 + 1], h, wj0v.y, y23[mt * 2 + 1]);
                    PACK2(h, h1);
                    FMA2(y01[mt * 2 + 1], h, wj1v.x, y01[mt * 2 + 1]);
                    FMA2(y23[mt * 2 + 1], h, wj1v.y, y23[mt * 2 + 1]);
                }
            }
        }

        #pragma unroll
        for (int ii = 0; ii < 4; ii++) {
            y01[ii] = bfly_add2(y01[ii], 1);
            y01[ii] = bfly_add2(y01[ii], 2);
            y23[ii] = bfly_add2(y23[ii], 1);
            y23[ii] = bfly_add2(y23[ii], 2);
        }

        {
            ull s01 = (q == 0) ? y01[0] : (q == 1) ? y01[1] : (q == 2) ? y01[2] : y01[3];
            ull s23 = (q == 0) ? y23[0] : (q == 1) ? y23[1] : (q == 2) ? y23[2] : y23[3];
            ull bb01 = *(const ull*)&b2s[0];
            ull bb23 = *(const ull*)&b2s[2];
            ADD2(s01, s01, bb01);
            ADD2(s23, s23, bb23);
            float4 res;
            UNPACK2(res.x, res.y, s01);
            UNPACK2(res.z, res.w, s23);
            const int b = m0 + (q >> 1) * 16 + (q & 1) * 8 + r;
            *(float4*)&out[(size_t)b * (NG * 4) + (size_t)g * 4] = res;
        }

        if (has_next) {
            float* W2n = smem + F_W2 + (buf ^ 1) * 256;
            float* b1n = smem + F_B1 + (buf ^ 1) * 64;
            float* b2n = smem + F_B2 + (buf ^ 1) * 8;
            if (t < 64) {
                int o = t >> 4, jq = t & 15;
                W2n[(4 * jq + 0) * 4 + o] = w2reg.x;
                W2n[(4 * jq + 1) * 4 + o] = w2reg.y;
                W2n[(4 * jq + 2) * 4 + o] = w2reg.z;
                W2n[(4 * jq + 3) * 4 + o] = w2reg.w;
            } else {
                b1n[t - 64] = b1reg;
            }
            if (t < 4) b2n[t] = b2reg;
        }
    }
}

extern "C" void kernel_launch(void* const* d_in, const int* in_sizes, int n_in,
                              void* d_out, int out_size)
{
    const float* day   = (const float*)d_in[0];
    const float* items = (const float*)d_in[1];
    const float* W1d   = (const float*)d_in[2];
    const float* W1v   = (const float*)d_in[3];
    const float* b1    = (const float*)d_in[4];
    const float* W2    = (const float*)d_in[5];
    const float* b2    = (const float*)d_in[6];
    float* out = (float*)d_out;

    cudaFuncSetAttribute(splitmlp_kernel,
                         cudaFuncAttributeMaxDynamicSharedMemorySize, SMEM_BYTES);
    splitmlp_kernel<<<NCTA, 128, SMEM_BYTES>>>(day, items, W1d, W1v, b1, W2, b2, out);
}